// round 3
// baseline (speedup 1.0000x reference)
#include <cuda_runtime.h>

// Problem constants
#define BB 16
#define NN 4096
#define CC 512
#define HH 8
#define DD 64
#define HWDIM 64
__device__ __constant__ float kSCALE = 0.35355339059327379f; // 64^-0.25

// Scratch (device globals; allocation inside kernel_launch is forbidden)
__device__ float g_qkv[(size_t)BB * NN * 3 * CC];        // [65536, 1536]
__device__ float g_A[(size_t)BB * HH * HWDIM * HWDIM];   // row attn  [bh,64,64]
__device__ float g_Bm[(size_t)BB * HH * HWDIM * HWDIM];  // col attn  [bh,64,64]
__device__ float g_Vt[(size_t)BB * HH * DD * HWDIM * HWDIM]; // [bh, c, t, w]
__device__ float g_attnT[(size_t)BB * CC * NN];          // [b, C, N] channel-major

// ---------------------------------------------------------------------------
// SGEMM NN: C[M,N] = A[M,K] @ B[K,N] + bias   (128x128 tile, BK=8, 256 thr)
// ---------------------------------------------------------------------------
__global__ __launch_bounds__(256) void sgemm_nn(
    const float* __restrict__ A, const float* __restrict__ B,
    const float* __restrict__ bias, float* __restrict__ C,
    int N, int K)
{
    __shared__ float As[8][128];
    __shared__ float Bs[8][128];
    const int tid = threadIdx.x;
    const int m0 = blockIdx.y * 128;
    const int n0 = blockIdx.x * 128;

    const int arow = tid >> 1;            // 0..127
    const int acol = (tid & 1) * 4;       // 0 or 4
    const int brow = tid >> 5;            // 0..7
    const int bcol = (tid & 31) * 4;

    const int tx = tid & 15;
    const int ty = tid >> 4;

    const float* Aptr = A + (size_t)(m0 + arow) * K + acol;
    const float* Bptr = B + (size_t)brow * N + n0 + bcol;

    float acc[8][8] = {};

    for (int k0 = 0; k0 < K; k0 += 8) {
        float4 av = *(const float4*)(Aptr + k0);
        float4 bv = *(const float4*)(Bptr + (size_t)k0 * N);
        As[acol + 0][arow] = av.x;
        As[acol + 1][arow] = av.y;
        As[acol + 2][arow] = av.z;
        As[acol + 3][arow] = av.w;
        *(float4*)&Bs[brow][bcol] = bv;
        __syncthreads();
#pragma unroll
        for (int k = 0; k < 8; ++k) {
            float af[8], bf[8];
            *(float4*)&af[0] = *(const float4*)&As[k][ty * 8];
            *(float4*)&af[4] = *(const float4*)&As[k][ty * 8 + 4];
            *(float4*)&bf[0] = *(const float4*)&Bs[k][tx * 8];
            *(float4*)&bf[4] = *(const float4*)&Bs[k][tx * 8 + 4];
#pragma unroll
            for (int i = 0; i < 8; ++i)
#pragma unroll
                for (int j = 0; j < 8; ++j)
                    acc[i][j] += af[i] * bf[j];
        }
        __syncthreads();
    }

#pragma unroll
    for (int i = 0; i < 8; ++i) {
        float* crow = C + (size_t)(m0 + ty * 8 + i) * N + n0 + tx * 8;
#pragma unroll
        for (int j = 0; j < 8; j += 4) {
            float4 o;
            o.x = acc[i][j + 0] + bias[n0 + tx * 8 + j + 0];
            o.y = acc[i][j + 1] + bias[n0 + tx * 8 + j + 1];
            o.z = acc[i][j + 2] + bias[n0 + tx * 8 + j + 2];
            o.w = acc[i][j + 3] + bias[n0 + tx * 8 + j + 3];
            *(float4*)(crow + j) = o;
        }
    }
}

// ---------------------------------------------------------------------------
// SGEMM TN for projection: A stored channel-major per batch: g_attnT[b][k][ntok]
// C[m, n] = sum_k At[b(m)][k][ntok(m)] * B[k][n] + bias[n];  N = K = 512
// ---------------------------------------------------------------------------
__global__ __launch_bounds__(256) void sgemm_tn_proj(
    const float* __restrict__ At, const float* __restrict__ B,
    const float* __restrict__ bias, float* __restrict__ C)
{
    const int N = 512, K = 512;
    __shared__ float As[8][128];
    __shared__ float Bs[8][128];
    const int tid = threadIdx.x;
    const int m0 = blockIdx.y * 128;
    const int n0 = blockIdx.x * 128;

    const int batch = m0 >> 12;      // m0 / 4096 (128 | 4096 so tiles don't cross)
    const int ntok0 = m0 & 4095;
    const float* Abase = At + (size_t)batch * CC * NN + ntok0;

    const int lk = tid >> 5;          // 0..7
    const int lm = (tid & 31) * 4;    // 0..124
    const int tx = tid & 15;
    const int ty = tid >> 4;

    float acc[8][8] = {};

    for (int k0 = 0; k0 < K; k0 += 8) {
        float4 av = *(const float4*)(Abase + (size_t)(k0 + lk) * NN + lm);
        float4 bv = *(const float4*)(B + (size_t)(k0 + lk) * N + n0 + lm);
        *(float4*)&As[lk][lm] = av;
        *(float4*)&Bs[lk][lm] = bv;
        __syncthreads();
#pragma unroll
        for (int k = 0; k < 8; ++k) {
            float af[8], bf[8];
            *(float4*)&af[0] = *(const float4*)&As[k][ty * 8];
            *(float4*)&af[4] = *(const float4*)&As[k][ty * 8 + 4];
            *(float4*)&bf[0] = *(const float4*)&Bs[k][tx * 8];
            *(float4*)&bf[4] = *(const float4*)&Bs[k][tx * 8 + 4];
#pragma unroll
            for (int i = 0; i < 8; ++i)
#pragma unroll
                for (int j = 0; j < 8; ++j)
                    acc[i][j] += af[i] * bf[j];
        }
        __syncthreads();
    }

#pragma unroll
    for (int i = 0; i < 8; ++i) {
        float* crow = C + (size_t)(m0 + ty * 8 + i) * N + n0 + tx * 8;
#pragma unroll
        for (int j = 0; j < 8; j += 4) {
            float4 o;
            o.x = acc[i][j + 0] + bias[n0 + tx * 8 + j + 0];
            o.y = acc[i][j + 1] + bias[n0 + tx * 8 + j + 1];
            o.z = acc[i][j + 2] + bias[n0 + tx * 8 + j + 2];
            o.w = acc[i][j + 3] + bias[n0 + tx * 8 + j + 3];
            *(float4*)(crow + j) = o;
        }
    }
}

// ---------------------------------------------------------------------------
// Axial attention logits + softmax.
// colmode=0 (row attn): token = i*64 + chunk   (contract over w=chunk, d)
// colmode=1 (col attn): token = chunk*64 + i   (contract over t=chunk, d)
// out[bh][i][j] = softmax_j( SCALE * sum Q[i]. K[j] )
// ---------------------------------------------------------------------------
__global__ __launch_bounds__(256) void axial_logits_softmax(
    const float* __restrict__ qkv, float* __restrict__ out, int colmode)
{
    const int bh = blockIdx.x;
    const int b = bh >> 3, h = bh & 7;
    const float* qbase = qkv + (size_t)b * NN * (3 * CC) + h * 64;

    __shared__ float Qs[64][65];
    __shared__ float Ks[64][65];

    const int tid = threadIdx.x;
    const int tx = tid & 15;
    const int ty = tid >> 4;

    float acc[4][4] = {};

    for (int chunk = 0; chunk < 64; ++chunk) {
#pragma unroll
        for (int p = 0; p < 4; ++p) {
            int row = ty + p * 16;
            int token = colmode ? (chunk * 64 + row) : (row * 64 + chunk);
            const float* qp = qbase + (size_t)token * (3 * CC) + tx * 4;
            float4 q4 = *(const float4*)qp;
            float4 k4 = *(const float4*)(qp + CC);
            Qs[row][tx * 4 + 0] = q4.x; Qs[row][tx * 4 + 1] = q4.y;
            Qs[row][tx * 4 + 2] = q4.z; Qs[row][tx * 4 + 3] = q4.w;
            Ks[row][tx * 4 + 0] = k4.x; Ks[row][tx * 4 + 1] = k4.y;
            Ks[row][tx * 4 + 2] = k4.z; Ks[row][tx * 4 + 3] = k4.w;
        }
        __syncthreads();
#pragma unroll 16
        for (int k = 0; k < 64; ++k) {
            float qf[4], kf[4];
#pragma unroll
            for (int i = 0; i < 4; ++i) qf[i] = Qs[ty * 4 + i][k];
#pragma unroll
            for (int j = 0; j < 4; ++j) kf[j] = Ks[tx * 4 + j][k];
#pragma unroll
            for (int i = 0; i < 4; ++i)
#pragma unroll
                for (int j = 0; j < 4; ++j)
                    acc[i][j] += qf[i] * kf[j];
        }
        __syncthreads();
    }

    // write scaled logits back into Qs, then softmax over j
#pragma unroll
    for (int i = 0; i < 4; ++i)
#pragma unroll
        for (int j = 0; j < 4; ++j)
            Qs[ty * 4 + i][tx * 4 + j] = acc[i][j] * kSCALE;
    __syncthreads();

    const int warp = tid >> 5, lane = tid & 31;
    float* ob = out + (size_t)bh * 4096;
    for (int r = warp; r < 64; r += 8) {
        float v0 = Qs[r][lane], v1 = Qs[r][lane + 32];
        float m = fmaxf(v0, v1);
#pragma unroll
        for (int o = 16; o > 0; o >>= 1)
            m = fmaxf(m, __shfl_xor_sync(0xffffffffu, m, o));
        float e0 = __expf(v0 - m), e1 = __expf(v1 - m);
        float s = e0 + e1;
#pragma unroll
        for (int o = 16; o > 0; o >>= 1)
            s += __shfl_xor_sync(0xffffffffu, s, o);
        float inv = 1.0f / s;
        ob[r * 64 + lane] = e0 * inv;
        ob[r * 64 + lane + 32] = e1 * inv;
    }
}

// ---------------------------------------------------------------------------
// Transpose V: qkv v-part [token, h*64+c] -> Vt[bh][c][t][w]
// one block per (t, bh)
// ---------------------------------------------------------------------------
__global__ __launch_bounds__(256) void transpose_v(
    const float* __restrict__ qkv, float* __restrict__ Vt)
{
    const int t = blockIdx.x;
    const int bh = blockIdx.y;
    const int b = bh >> 3, h = bh & 7;
    __shared__ float tile[64][65];
    const int tid = threadIdx.x;
    const int tx = tid & 15, ty = tid >> 4;

    const float* vbase = qkv + (size_t)b * NN * (3 * CC) + 2 * CC + h * 64;
#pragma unroll
    for (int p = 0; p < 4; ++p) {
        int w = ty + p * 16;
        float4 v4 = *(const float4*)(vbase + (size_t)(t * 64 + w) * (3 * CC) + tx * 4);
        tile[w][tx * 4 + 0] = v4.x; tile[w][tx * 4 + 1] = v4.y;
        tile[w][tx * 4 + 2] = v4.z; tile[w][tx * 4 + 3] = v4.w;
    }
    __syncthreads();

    float* obase = Vt + (size_t)bh * 64 * 4096 + t * 64;
#pragma unroll
    for (int p = 0; p < 4; ++p) {
        int c = ty + p * 16;
        float4 o;
        o.x = tile[tx * 4 + 0][c];
        o.y = tile[tx * 4 + 1][c];
        o.z = tile[tx * 4 + 2][c];
        o.w = tile[tx * 4 + 3][c];
        *(float4*)(obase + (size_t)c * 4096 + tx * 4) = o;
    }
}

// ---------------------------------------------------------------------------
// Coupled combine: one block per (c, bh).
//   T1[t][u] = sum_w Vc[t][w] * bm[u][w]
//   O[i][w]  = sum_j a[i][j] * T1[j][w]
// write O to attnT[b][h*64+c][i*64+w]  (== attnT[(bh*64+c)*4096 + ...])
// ---------------------------------------------------------------------------
__global__ __launch_bounds__(256) void combine_kernel(
    const float* __restrict__ Abuf, const float* __restrict__ Bmbuf,
    const float* __restrict__ Vt, float* __restrict__ attnT)
{
    extern __shared__ float sm[];
    float (*As_)[65] = reinterpret_cast<float (*)[65]>(sm);
    float (*Bs_)[65] = reinterpret_cast<float (*)[65]>(sm + 64 * 65);
    float (*Vs)[65]  = reinterpret_cast<float (*)[65]>(sm + 2 * 64 * 65);
    float (*Ts)[65]  = reinterpret_cast<float (*)[65]>(sm + 3 * 64 * 65);

    const int c = blockIdx.x;
    const int bh = blockIdx.y;
    const int tid = threadIdx.x;
    const int tx = tid & 15, ty = tid >> 4;

    const float* ab = Abuf + (size_t)bh * 4096;
    const float* bb = Bmbuf + (size_t)bh * 4096;
    const float* vb = Vt + ((size_t)bh * 64 + c) * 4096;

#pragma unroll
    for (int p = 0; p < 4; ++p) {
        int row = ty + p * 16;
        float4 a4 = *(const float4*)(ab + row * 64 + tx * 4);
        float4 b4 = *(const float4*)(bb + row * 64 + tx * 4);
        float4 v4 = *(const float4*)(vb + row * 64 + tx * 4);
        As_[row][tx * 4 + 0] = a4.x; As_[row][tx * 4 + 1] = a4.y;
        As_[row][tx * 4 + 2] = a4.z; As_[row][tx * 4 + 3] = a4.w;
        Bs_[row][tx * 4 + 0] = b4.x; Bs_[row][tx * 4 + 1] = b4.y;
        Bs_[row][tx * 4 + 2] = b4.z; Bs_[row][tx * 4 + 3] = b4.w;
        Vs[row][tx * 4 + 0] = v4.x; Vs[row][tx * 4 + 1] = v4.y;
        Vs[row][tx * 4 + 2] = v4.z; Vs[row][tx * 4 + 3] = v4.w;
    }
    __syncthreads();

    // phase 1: T1 = Vc @ bm^T
    {
        float acc[4][4] = {};
#pragma unroll 16
        for (int w = 0; w < 64; ++w) {
            float vf[4], bf[4];
#pragma unroll
            for (int i = 0; i < 4; ++i) vf[i] = Vs[ty * 4 + i][w];
#pragma unroll
            for (int j = 0; j < 4; ++j) bf[j] = Bs_[tx * 4 + j][w];
#pragma unroll
            for (int i = 0; i < 4; ++i)
#pragma unroll
                for (int j = 0; j < 4; ++j)
                    acc[i][j] += vf[i] * bf[j];
        }
#pragma unroll
        for (int i = 0; i < 4; ++i)
#pragma unroll
            for (int j = 0; j < 4; ++j)
                Ts[ty * 4 + i][tx * 4 + j] = acc[i][j];
    }
    __syncthreads();

    // phase 2: O = a @ T1
    float acc[4][4] = {};
#pragma unroll 16
    for (int j = 0; j < 64; ++j) {
        float af[4], tf[4];
#pragma unroll
        for (int i = 0; i < 4; ++i) af[i] = As_[ty * 4 + i][j];
#pragma unroll
        for (int jj = 0; jj < 4; ++jj) tf[jj] = Ts[j][tx * 4 + jj];
#pragma unroll
        for (int i = 0; i < 4; ++i)
#pragma unroll
            for (int jj = 0; jj < 4; ++jj)
                acc[i][jj] += af[i] * tf[jj];
    }

    float* ob = attnT + ((size_t)bh * 64 + c) * 4096;
#pragma unroll
    for (int i = 0; i < 4; ++i) {
        float4 o;
        o.x = acc[i][0]; o.y = acc[i][1]; o.z = acc[i][2]; o.w = acc[i][3];
        *(float4*)(ob + (ty * 4 + i) * 64 + tx * 4) = o;
    }
}

// ---------------------------------------------------------------------------
extern "C" void kernel_launch(void* const* d_in, const int* in_sizes, int n_in,
                              void* d_out, int out_size)
{
    const float* x     = (const float*)d_in[0];
    const float* Wqkv  = (const float*)d_in[1];
    const float* bqkv  = (const float*)d_in[2];
    const float* Wproj = (const float*)d_in[3];
    const float* bproj = (const float*)d_in[4];
    float* out = (float*)d_out;

    float *qkv, *Ab, *Bmb, *Vt, *attnT;
    cudaGetSymbolAddress((void**)&qkv, g_qkv);
    cudaGetSymbolAddress((void**)&Ab, g_A);
    cudaGetSymbolAddress((void**)&Bmb, g_Bm);
    cudaGetSymbolAddress((void**)&Vt, g_Vt);
    cudaGetSymbolAddress((void**)&attnT, g_attnT);

    // 1. QKV projection: [65536,512] @ [512,1536]
    sgemm_nn<<<dim3(1536 / 128, (BB * NN) / 128), 256>>>(x, Wqkv, bqkv, qkv, 3 * CC, CC);

    // 2+3. axial attentions (row / col), softmaxed
    axial_logits_softmax<<<BB * HH, 256>>>(qkv, Ab, 0);
    axial_logits_softmax<<<BB * HH, 256>>>(qkv, Bmb, 1);

    // 4. transpose V to channel-major
    transpose_v<<<dim3(64, BB * HH), 256>>>(qkv, Vt);

    // 5. coupled combine -> attnT [B, C, N]
    cudaFuncSetAttribute(combine_kernel, cudaFuncAttributeMaxDynamicSharedMemorySize,
                         4 * 64 * 65 * sizeof(float));
    combine_kernel<<<dim3(64, BB * HH), 256, 4 * 64 * 65 * sizeof(float)>>>(Ab, Bmb, Vt, attnT);

    // 6. projection: attnT^T @ Wproj + bproj -> out [B,N,C]
    sgemm_tn_proj<<<dim3(512 / 128, (BB * NN) / 128), 256>>>(attnT, Wproj, bproj, out);
}